// round 5
// baseline (speedup 1.0000x reference)
#include <cuda_runtime.h>
#include <cuda_bf16.h>
#include <cstdint>

// ESN collapsed op: out[bt, r] = (1 - lr) * tanh( sum_i x[bt,i] * w[r,i] )
// B*T = 1,048,576 rows, I = 8, R = 128. Store-stream bound (~537MB out,
// floor ~79us). cp.async double-buffered x staging; warp = half row,
// lane owns (r0, r0+1); full-tile fast path, pointer-walk addressing.

__device__ __forceinline__ unsigned long long pk2(float lo, float hi) {
    unsigned long long r;
    asm("mov.b64 %0, {%1, %2};" : "=l"(r) : "f"(lo), "f"(hi));
    return r;
}
__device__ __forceinline__ void upk2(float& lo, float& hi, unsigned long long v) {
    asm("mov.b64 {%0, %1}, %2;" : "=f"(lo), "=f"(hi) : "l"(v));
}
__device__ __forceinline__ unsigned long long mul2(unsigned long long a, unsigned long long b) {
    unsigned long long r;
    asm("mul.rn.f32x2 %0, %1, %2;" : "=l"(r) : "l"(a), "l"(b));
    return r;
}
__device__ __forceinline__ unsigned long long fma2(unsigned long long a, unsigned long long b,
                                                   unsigned long long c) {
    unsigned long long r;
    asm("fma.rn.f32x2 %0, %1, %2, %3;" : "=l"(r) : "l"(a), "l"(b), "l"(c));
    return r;
}
__device__ __forceinline__ float tanh_ap(float x) {
    float y;
    asm("tanh.approx.f32 %0, %1;" : "=f"(y) : "f"(x));
    return y;
}

static constexpr int TILE = 128;           // rows per stage per block
static constexpr int TILE_F = TILE * 8;    // floats per stage (1024 = 4KB)

__global__ void __launch_bounds__(256, 7) ESN_11390253269642_kernel(
    const float* __restrict__ x,     // [BT, 8]
    const float* __restrict__ w,     // [128, 8]
    const float* __restrict__ lrp,   // [1]
    float* __restrict__ out,         // [BT, 128]
    int bt_total)
{
    __shared__ float xs[2][TILE_F];

    const int tid  = threadIdx.x;
    const int lane = tid & 31;
    const int wid  = tid >> 5;           // 0..7
    const int half = wid & 1;            // which 64-wide half of the row
    const int wrow = wid >> 1;           // 0..3: row offset within stride-4 groups
    const float s = 1.0f - __ldg(lrp);

    // This lane owns r0 = half*64 + lane*2 and r1 = r0+1.
    unsigned long long w0[4], w1[4];
    {
        const int r0 = half * 64 + lane * 2;
        const float4* p0 = reinterpret_cast<const float4*>(w + r0 * 8);
        float4 a = __ldg(p0), b = __ldg(p0 + 1);
        w0[0] = pk2(a.x, a.y); w0[1] = pk2(a.z, a.w);
        w0[2] = pk2(b.x, b.y); w0[3] = pk2(b.z, b.w);
        const float4* p1 = reinterpret_cast<const float4*>(w + (r0 + 1) * 8);
        a = __ldg(p1); b = __ldg(p1 + 1);
        w1[0] = pk2(a.x, a.y); w1[1] = pk2(a.z, a.w);
        w1[2] = pk2(b.x, b.y); w1[3] = pk2(b.z, b.w);
    }

    const long long total_f = (long long)bt_total * 8;
    const int ntiles = (bt_total + TILE - 1) / TILE;

    // cp.async: 256 threads x 16B = 4KB = one full tile (L2-only, stream)
    auto issue_tile = [&](int tile, int buf) {
        long long off = (long long)tile * TILE_F + tid * 4;
        if (off < total_f) {
            uint32_t dst = (uint32_t)__cvta_generic_to_shared(&xs[buf][tid * 4]);
            const float* src = x + off;
            asm volatile("cp.async.cg.shared.global [%0], [%1], 16;"
                         :: "r"(dst), "l"(src));
        }
    };

    int tile = blockIdx.x;
    int buf = 0;
    if (tile < ntiles) issue_tile(tile, 0);
    asm volatile("cp.async.commit_group;");

    for (; tile < ntiles; tile += gridDim.x) {
        int next = tile + gridDim.x;
        if (next < ntiles) issue_tile(next, buf ^ 1);
        asm volatile("cp.async.commit_group;");
        asm volatile("cp.async.wait_group 1;");
        __syncthreads();

        uint32_t xa = (uint32_t)__cvta_generic_to_shared(&xs[buf][wrow * 8]);
        float* op = out + (size_t)(tile * TILE + wrow) * 128 + half * 64 + lane * 2;

        if (tile * TILE + TILE <= bt_total) {
            // full tile: no per-row predicates
#pragma unroll 8
            for (int j = 0; j < 32; j++) {
                unsigned long long xv0, xv1, xv2, xv3;
                asm volatile("ld.shared.v2.u64 {%0, %1}, [%2];"
                             : "=l"(xv0), "=l"(xv1) : "r"(xa));
                asm volatile("ld.shared.v2.u64 {%0, %1}, [%2];"
                             : "=l"(xv2), "=l"(xv3) : "r"(xa + 16));
                xa += 128;                      // 4 rows * 32B

                unsigned long long acc0 = mul2(w0[0], xv0);
                unsigned long long acc1 = mul2(w1[0], xv0);
                acc0 = fma2(w0[1], xv1, acc0);
                acc1 = fma2(w1[1], xv1, acc1);
                acc0 = fma2(w0[2], xv2, acc0);
                acc1 = fma2(w1[2], xv2, acc1);
                acc0 = fma2(w0[3], xv3, acc0);
                acc1 = fma2(w1[3], xv3, acc1);

                float lo0, hi0, lo1, hi1;
                upk2(lo0, hi0, acc0);
                upk2(lo1, hi1, acc1);
                float2 o;
                o.x = s * tanh_ap(lo0 + hi0);
                o.y = s * tanh_ap(lo1 + hi1);
                __stcs(reinterpret_cast<float2*>(op), o);
                op += 4 * 128;                  // 4 rows of 128 floats
            }
        } else {
            const int rowlim = bt_total - tile * TILE;
            for (int j = 0; j < 32; j++) {
                if (wrow + j * 4 >= rowlim) break;
                unsigned long long xv0, xv1, xv2, xv3;
                asm volatile("ld.shared.v2.u64 {%0, %1}, [%2];"
                             : "=l"(xv0), "=l"(xv1) : "r"(xa));
                asm volatile("ld.shared.v2.u64 {%0, %1}, [%2];"
                             : "=l"(xv2), "=l"(xv3) : "r"(xa + 16));
                xa += 128;

                unsigned long long acc0 = mul2(w0[0], xv0);
                unsigned long long acc1 = mul2(w1[0], xv0);
                acc0 = fma2(w0[1], xv1, acc0);
                acc1 = fma2(w1[1], xv1, acc1);
                acc0 = fma2(w0[2], xv2, acc0);
                acc1 = fma2(w1[2], xv2, acc1);
                acc0 = fma2(w0[3], xv3, acc0);
                acc1 = fma2(w1[3], xv3, acc1);

                float lo0, hi0, lo1, hi1;
                upk2(lo0, hi0, acc0);
                upk2(lo1, hi1, acc1);
                float2 o;
                o.x = s * tanh_ap(lo0 + hi0);
                o.y = s * tanh_ap(lo1 + hi1);
                __stcs(reinterpret_cast<float2*>(op), o);
                op += 4 * 128;
            }
        }
        __syncthreads();
        buf ^= 1;
    }
}

extern "C" void kernel_launch(void* const* d_in, const int* in_sizes, int n_in,
                              void* d_out, int out_size)
{
    const float* x   = (const float*)d_in[0];   // [B, T, I] fp32
    const float* w   = (const float*)d_in[1];   // [R, I] fp32
    // d_in[2] = d, unused (contributes exactly 0 in the reference)
    const float* lr  = (const float*)d_in[3];   // [1] fp32
    float* out = (float*)d_out;

    const int bt_total = in_sizes[0] / 8;       // B*T rows

    int ntiles = (bt_total + TILE - 1) / TILE;
    int blocks = 1036;                           // 7 blocks/SM x 148 SMs
    if (blocks > ntiles) blocks = ntiles;
    if (blocks < 1) blocks = 1;
    ESN_11390253269642_kernel<<<blocks, 256>>>(x, w, lr, out, bt_total);
}

// round 6
// speedup vs baseline: 1.0051x; 1.0051x over previous
#include <cuda_runtime.h>
#include <cuda_bf16.h>
#include <cstdint>

// ESN collapsed op: out[bt, r] = (1 - lr) * tanh( sum_i x[bt,i] * w[r,i] )
// B*T = 1,048,576 rows, I = 8, R = 128. Store-stream bound (~537MB out,
// floor ~80us). cp.async double-buffered x staging; warp = half row,
// lane owns (r0, r0+1). Full-tile fast path + pointer-walk addressing,
// 6 blocks/SM (reg cap 42: R4's verified sweet spot; cap 32 regressed).

__device__ __forceinline__ unsigned long long pk2(float lo, float hi) {
    unsigned long long r;
    asm("mov.b64 %0, {%1, %2};" : "=l"(r) : "f"(lo), "f"(hi));
    return r;
}
__device__ __forceinline__ void upk2(float& lo, float& hi, unsigned long long v) {
    asm("mov.b64 {%0, %1}, %2;" : "=f"(lo), "=f"(hi) : "l"(v));
}
__device__ __forceinline__ unsigned long long mul2(unsigned long long a, unsigned long long b) {
    unsigned long long r;
    asm("mul.rn.f32x2 %0, %1, %2;" : "=l"(r) : "l"(a), "l"(b));
    return r;
}
__device__ __forceinline__ unsigned long long fma2(unsigned long long a, unsigned long long b,
                                                   unsigned long long c) {
    unsigned long long r;
    asm("fma.rn.f32x2 %0, %1, %2, %3;" : "=l"(r) : "l"(a), "l"(b), "l"(c));
    return r;
}
__device__ __forceinline__ float tanh_ap(float x) {
    float y;
    asm("tanh.approx.f32 %0, %1;" : "=f"(y) : "f"(x));
    return y;
}

static constexpr int TILE = 128;           // rows per stage per block
static constexpr int TILE_F = TILE * 8;    // floats per stage (1024 = 4KB)

__global__ void __launch_bounds__(256, 6) ESN_11390253269642_kernel(
    const float* __restrict__ x,     // [BT, 8]
    const float* __restrict__ w,     // [128, 8]
    const float* __restrict__ lrp,   // [1]
    float* __restrict__ out,         // [BT, 128]
    int bt_total)
{
    __shared__ float xs[2][TILE_F];

    const int tid  = threadIdx.x;
    const int lane = tid & 31;
    const int wid  = tid >> 5;           // 0..7
    const int half = wid & 1;            // which 64-wide half of the row
    const int wrow = wid >> 1;           // 0..3: row offset within stride-4 groups
    const float s = 1.0f - __ldg(lrp);

    // This lane owns r0 = half*64 + lane*2 and r1 = r0+1.
    unsigned long long w0[4], w1[4];
    {
        const int r0 = half * 64 + lane * 2;
        const float4* p0 = reinterpret_cast<const float4*>(w + r0 * 8);
        float4 a = __ldg(p0), b = __ldg(p0 + 1);
        w0[0] = pk2(a.x, a.y); w0[1] = pk2(a.z, a.w);
        w0[2] = pk2(b.x, b.y); w0[3] = pk2(b.z, b.w);
        const float4* p1 = reinterpret_cast<const float4*>(w + (r0 + 1) * 8);
        a = __ldg(p1); b = __ldg(p1 + 1);
        w1[0] = pk2(a.x, a.y); w1[1] = pk2(a.z, a.w);
        w1[2] = pk2(b.x, b.y); w1[3] = pk2(b.z, b.w);
    }

    const long long total_f = (long long)bt_total * 8;
    const int ntiles = (bt_total + TILE - 1) / TILE;

    // cp.async: 256 threads x 16B = 4KB = one full tile
    auto issue_tile = [&](int tile, int buf) {
        long long off = (long long)tile * TILE_F + tid * 4;
        if (off < total_f) {
            uint32_t dst = (uint32_t)__cvta_generic_to_shared(&xs[buf][tid * 4]);
            const float* src = x + off;
            asm volatile("cp.async.ca.shared.global [%0], [%1], 16;"
                         :: "r"(dst), "l"(src));
        }
    };

    int tile = blockIdx.x;
    int buf = 0;
    if (tile < ntiles) issue_tile(tile, 0);
    asm volatile("cp.async.commit_group;");

    for (; tile < ntiles; tile += gridDim.x) {
        int next = tile + gridDim.x;
        if (next < ntiles) issue_tile(next, buf ^ 1);
        asm volatile("cp.async.commit_group;");
        asm volatile("cp.async.wait_group 1;");
        __syncthreads();

        uint32_t xa = (uint32_t)__cvta_generic_to_shared(&xs[buf][wrow * 8]);
        float* op = out + (size_t)(tile * TILE + wrow) * 128 + half * 64 + lane * 2;

        if (tile * TILE + TILE <= bt_total) {
            // full tile: no per-row predicates
#pragma unroll 8
            for (int j = 0; j < 32; j++) {
                unsigned long long xv0, xv1, xv2, xv3;
                asm volatile("ld.shared.v2.u64 {%0, %1}, [%2];"
                             : "=l"(xv0), "=l"(xv1) : "r"(xa));
                asm volatile("ld.shared.v2.u64 {%0, %1}, [%2];"
                             : "=l"(xv2), "=l"(xv3) : "r"(xa + 16));
                xa += 128;                      // 4 rows * 32B

                unsigned long long acc0 = mul2(w0[0], xv0);
                unsigned long long acc1 = mul2(w1[0], xv0);
                acc0 = fma2(w0[1], xv1, acc0);
                acc1 = fma2(w1[1], xv1, acc1);
                acc0 = fma2(w0[2], xv2, acc0);
                acc1 = fma2(w1[2], xv2, acc1);
                acc0 = fma2(w0[3], xv3, acc0);
                acc1 = fma2(w1[3], xv3, acc1);

                float lo0, hi0, lo1, hi1;
                upk2(lo0, hi0, acc0);
                upk2(lo1, hi1, acc1);
                float2 o;
                o.x = s * tanh_ap(lo0 + hi0);
                o.y = s * tanh_ap(lo1 + hi1);
                __stcs(reinterpret_cast<float2*>(op), o);
                op += 4 * 128;                  // 4 rows of 128 floats
            }
        } else {
            const int rowlim = bt_total - tile * TILE;
            for (int j = 0; j < 32; j++) {
                if (wrow + j * 4 >= rowlim) break;
                unsigned long long xv0, xv1, xv2, xv3;
                asm volatile("ld.shared.v2.u64 {%0, %1}, [%2];"
                             : "=l"(xv0), "=l"(xv1) : "r"(xa));
                asm volatile("ld.shared.v2.u64 {%0, %1}, [%2];"
                             : "=l"(xv2), "=l"(xv3) : "r"(xa + 16));
                xa += 128;

                unsigned long long acc0 = mul2(w0[0], xv0);
                unsigned long long acc1 = mul2(w1[0], xv0);
                acc0 = fma2(w0[1], xv1, acc0);
                acc1 = fma2(w1[1], xv1, acc1);
                acc0 = fma2(w0[2], xv2, acc0);
                acc1 = fma2(w1[2], xv2, acc1);
                acc0 = fma2(w0[3], xv3, acc0);
                acc1 = fma2(w1[3], xv3, acc1);

                float lo0, hi0, lo1, hi1;
                upk2(lo0, hi0, acc0);
                upk2(lo1, hi1, acc1);
                float2 o;
                o.x = s * tanh_ap(lo0 + hi0);
                o.y = s * tanh_ap(lo1 + hi1);
                __stcs(reinterpret_cast<float2*>(op), o);
                op += 4 * 128;
            }
        }
        __syncthreads();
        buf ^= 1;
    }
}

extern "C" void kernel_launch(void* const* d_in, const int* in_sizes, int n_in,
                              void* d_out, int out_size)
{
    const float* x   = (const float*)d_in[0];   // [B, T, I] fp32
    const float* w   = (const float*)d_in[1];   // [R, I] fp32
    // d_in[2] = d, unused (contributes exactly 0 in the reference)
    const float* lr  = (const float*)d_in[3];   // [1] fp32
    float* out = (float*)d_out;

    const int bt_total = in_sizes[0] / 8;       // B*T rows

    int ntiles = (bt_total + TILE - 1) / TILE;
    int blocks = 888;                            // 6 blocks/SM x 148 SMs
    if (blocks > ntiles) blocks = ntiles;
    if (blocks < 1) blocks = 1;
    ESN_11390253269642_kernel<<<blocks, 256>>>(x, w, lr, out, bt_total);
}